// round 16
// baseline (speedup 1.0000x reference)
#include <cuda_runtime.h>
#include <math_constants.h>

// x:    (16, 64, 512, 512) float32
// mask: (16, 1, 512, 512) int32
// out:  (16, 64) float32
#define NB 16
#define NC 64
#define HW (512 * 512)                 // 262144
#define CHUNKS 16                      // chunks per (b,c) row
#define THREADS 256
#define F4_PER_CHUNK (HW / 4 / CHUNKS) // 4096 float4 per chunk
#define ITERS (F4_PER_CHUNK / THREADS) // 16 float4 per thread
#define PRE 8                          // x float4 prefetched before gridsync
#define NROWS (NB * NC)                // 1024
#define NCID (NB * CHUNKS)             // 256 (b,chunk) pairs

// Bitmask: uint2 per (cid, thread), thread-private nibble order.
// bits0 nibble i (i<8) / bits1 nibble i-8 cover float4 idx = i*256 + t.
__device__ uint2 g_bits2[NCID * THREADS];       // 512 KiB, overwritten each launch
__device__ int   g_nonempty[NB];                // 0-init; monotone OR, replay-safe
__device__ float g_partial[NROWS * CHUNKS];     // overwritten each launch
__device__ int   g_ctr[NROWS];                  // self-resetting

// ---- Pack: one block per (b,chunk); thread packs its own 64 positions ----
__global__ void __launch_bounds__(THREADS)
pack_kernel(const int4* __restrict__ mask4) {
    int cid   = blockIdx.x;             // b*CHUNKS + chunk
    int b     = cid >> 4;
    int chunk = cid & (CHUNKS - 1);
    int t     = threadIdx.x;

    const int4* mr = mask4 + (size_t)b * (HW / 4)
                           + (size_t)chunk * F4_PER_CHUNK;
    unsigned bits0 = 0, bits1 = 0;
#pragma unroll
    for (int i = 0; i < ITERS; i++) {
        int4 mv = __ldg(mr + i * THREADS + t);
        unsigned nib = (unsigned)(mv.x != 0)
                     | ((unsigned)(mv.y != 0) << 1)
                     | ((unsigned)(mv.z != 0) << 2)
                     | ((unsigned)(mv.w != 0) << 3);
        if (i < 8) bits0 |= nib << (4 * i);
        else       bits1 |= nib << (4 * (i - 8));
    }
    g_bits2[cid * THREADS + t] = make_uint2(bits0, bits1);

    int bany = __syncthreads_or((int)((bits0 | bits1) != 0));
    if (t == 0 && bany) atomicOr(&g_nonempty[b], 1);

    cudaTriggerProgrammaticLaunchCompletion();
}

// ---- Pool: prefetch x BEFORE gridsync so it overlaps pack execution ----
__global__ void __launch_bounds__(THREADS)
pool_kernel(const float4* __restrict__ x, float* __restrict__ out) {
    int blk   = blockIdx.x;
    int chunk = blk & (CHUNKS - 1);
    int row   = blk >> 4;               // b*NC + c
    int b     = row >> 6;
    int cid   = b * CHUNKS + chunk;
    int t     = threadIdx.x;
    int lane  = t & 31;

    const float4* xr = x + (size_t)row * (HW / 4) + (size_t)chunk * F4_PER_CHUNK;

    // Prefetch: x does NOT depend on pack output -> issue before the PDL wait.
    float4 xv[PRE];
#pragma unroll
    for (int i = 0; i < PRE; i++)
        xv[i] = __ldg(xr + i * THREADS + t);

    // Wait for pack grid only where its output is first consumed.
    cudaGridDependencySynchronize();

    uint2 bb = g_bits2[cid * THREADS + t];      // 8B coalesced, L2-resident
    unsigned bits0 = bb.x, bits1 = bb.y;

    float vmax = -CUDART_INF_F;
#pragma unroll
    for (int i = 0; i < PRE; i++) {             // consume prefetched half
        unsigned nib = (bits0 >> (4 * i)) & 0xFu;
        vmax = fmaxf(vmax, (nib & 1u) ? xv[i].x : -CUDART_INF_F);
        vmax = fmaxf(vmax, (nib & 2u) ? xv[i].y : -CUDART_INF_F);
        vmax = fmaxf(vmax, (nib & 4u) ? xv[i].z : -CUDART_INF_F);
        vmax = fmaxf(vmax, (nib & 8u) ? xv[i].w : -CUDART_INF_F);
    }
#pragma unroll
    for (int i = PRE; i < ITERS; i++) {         // stream remaining half
        unsigned nib = (bits1 >> (4 * (i - 8))) & 0xFu;
        float4 xw = __ldg(xr + i * THREADS + t);
        vmax = fmaxf(vmax, (nib & 1u) ? xw.x : -CUDART_INF_F);
        vmax = fmaxf(vmax, (nib & 2u) ? xw.y : -CUDART_INF_F);
        vmax = fmaxf(vmax, (nib & 4u) ? xw.z : -CUDART_INF_F);
        vmax = fmaxf(vmax, (nib & 8u) ? xw.w : -CUDART_INF_F);
    }

#pragma unroll
    for (int o = 16; o; o >>= 1)
        vmax = fmaxf(vmax, __shfl_xor_sync(0xffffffffu, vmax, o));

    __shared__ float smax[THREADS / 32];
    __shared__ bool  slast;
    if (lane == 0) smax[t >> 5] = vmax;
    __syncthreads();

    if (t == 0) {
        float m = smax[0];
#pragma unroll
        for (int w = 1; w < THREADS / 32; w++) m = fmaxf(m, smax[w]);
        g_partial[row * CHUNKS + chunk] = m;
        __threadfence();
        int old = atomicAdd(&g_ctr[row], 1);
        slast = (old == CHUNKS - 1);
    }
    __syncthreads();

    // Last block of this row: 16 threads reduce 16 partials (partial mask!),
    // apply empty-mask fixup, write out, reset counter for graph replay.
    if (slast && t < CHUNKS) {
        float v = g_partial[row * CHUNKS + t];
#pragma unroll
        for (int o = CHUNKS / 2; o; o >>= 1)
            v = fmaxf(v, __shfl_xor_sync(0xffffu, v, o));
        if (t == 0) {
            out[row] = g_nonempty[b] ? v : 0.0f;
            g_ctr[row] = 0;
        }
    }
}

extern "C" void kernel_launch(void* const* d_in, const int* in_sizes, int n_in,
                              void* d_out, int out_size) {
    const float4* x     = (const float4*)d_in[0];
    const int4*   mask4 = (const int4*)d_in[1];
    float*        out   = (float*)d_out;

    pack_kernel<<<NCID, THREADS>>>(mask4);

    // Pool with PDL: launch may begin while pack is still draining.
    cudaLaunchAttribute attr[1];
    attr[0].id = cudaLaunchAttributeProgrammaticStreamSerialization;
    attr[0].val.programmaticStreamSerializationAllowed = 1;
    cudaLaunchConfig_t cfg = {};
    cfg.gridDim  = dim3(NROWS * CHUNKS);
    cfg.blockDim = dim3(THREADS);
    cfg.dynamicSmemBytes = 0;
    cfg.stream = 0;
    cfg.attrs = attr;
    cfg.numAttrs = 1;
    cudaError_t e = cudaLaunchKernelEx(&cfg, pool_kernel, x, out);
    if (e != cudaSuccess) {
        // Fallback: plain serialized launch (still correct).
        pool_kernel<<<NROWS * CHUNKS, THREADS>>>(x, out);
    }
}

// round 17
// speedup vs baseline: 1.0372x; 1.0372x over previous
#include <cuda_runtime.h>
#include <math_constants.h>

// x:    (16, 64, 512, 512) float32
// mask: (16, 1, 512, 512) int32
// out:  (16, 64) float32
#define NB 16
#define NC 64
#define HW (512 * 512)                 // 262144
#define CHUNKS 16                      // chunks per (b,c) row
#define THREADS 256
#define F4_PER_CHUNK (HW / 4 / CHUNKS) // 4096 float4 per chunk
#define ITERS (F4_PER_CHUNK / THREADS) // 16 float4 per thread
#define NROWS (NB * NC)                // 1024
#define NCID (NB * CHUNKS)             // 256 (b,chunk) pairs
#define PACKQ 4                        // quarter-splits of each pack chunk
#define PITERS (ITERS / PACKQ)         // 4 int4 per pack thread

// Bitmask: uint2 per (cid, pool-thread). ushort q within it covers nibbles
// i = 4q..4q+3 (nibble i gates float4 idx = i*256 + t).
__device__ uint2 g_bits2[NCID * THREADS];       // 512 KiB, overwritten each launch
__device__ int   g_nonempty[NB];                // 0-init; monotone OR, replay-safe
__device__ float g_partial[NROWS * CHUNKS];     // overwritten each launch
__device__ int   g_ctr[NROWS];                  // self-resetting

// ---- Pack: 4 blocks per (b,chunk); thread packs 16 bits -> one ushort ----
__global__ void __launch_bounds__(THREADS)
pack_kernel(const int4* __restrict__ mask4) {
    int bid   = blockIdx.x;             // cid*PACKQ + q
    int q     = bid & (PACKQ - 1);
    int cid   = bid >> 2;               // b*CHUNKS + chunk
    int b     = cid >> 4;
    int chunk = cid & (CHUNKS - 1);
    int t     = threadIdx.x;

    const int4* mr = mask4 + (size_t)b * (HW / 4)
                           + (size_t)chunk * F4_PER_CHUNK;
    unsigned hb = 0;
#pragma unroll
    for (int j = 0; j < PITERS; j++) {
        int i = q * PITERS + j;         // nibble index 0..15
        int4 mv = __ldg(mr + i * THREADS + t);
        unsigned nib = (unsigned)(mv.x != 0)
                     | ((unsigned)(mv.y != 0) << 1)
                     | ((unsigned)(mv.z != 0) << 2)
                     | ((unsigned)(mv.w != 0) << 3);
        hb |= nib << (4 * j);
    }
    ((unsigned short*)g_bits2)[(size_t)(cid * THREADS + t) * PACKQ + q] =
        (unsigned short)hb;

    int bany = __syncthreads_or((int)(hb != 0));
    if (t == 0 && bany) atomicOr(&g_nonempty[b], 1);
}

// ---- Pool: one block per (row, chunk); mask = one 8B load per thread ----
__global__ void __launch_bounds__(THREADS)
pool_kernel(const float4* __restrict__ x, float* __restrict__ out) {
    int blk   = blockIdx.x;
    int chunk = blk & (CHUNKS - 1);
    int row   = blk >> 4;               // b*NC + c
    int b     = row >> 6;
    int cid   = b * CHUNKS + chunk;
    int t     = threadIdx.x;
    int lane  = t & 31;

    uint2 bb = g_bits2[cid * THREADS + t];      // 8B coalesced, L2-resident
    unsigned bits0 = bb.x, bits1 = bb.y;        // nibble i<8 / i>=8

    const float4* xr = x + (size_t)row * (HW / 4) + (size_t)chunk * F4_PER_CHUNK;
    float vmax = -CUDART_INF_F;
#pragma unroll
    for (int i = 0; i < ITERS; i++) {
        unsigned nib = ((i < 8) ? (bits0 >> (4 * i))
                                : (bits1 >> (4 * (i - 8)))) & 0xFu;
        float4 xv = __ldcs(xr + i * THREADS + t);   // streaming: evict-first
        vmax = fmaxf(vmax, (nib & 1u) ? xv.x : -CUDART_INF_F);
        vmax = fmaxf(vmax, (nib & 2u) ? xv.y : -CUDART_INF_F);
        vmax = fmaxf(vmax, (nib & 4u) ? xv.z : -CUDART_INF_F);
        vmax = fmaxf(vmax, (nib & 8u) ? xv.w : -CUDART_INF_F);
    }

#pragma unroll
    for (int o = 16; o; o >>= 1)
        vmax = fmaxf(vmax, __shfl_xor_sync(0xffffffffu, vmax, o));

    __shared__ float smax[THREADS / 32];
    __shared__ bool  slast;
    if (lane == 0) smax[t >> 5] = vmax;
    __syncthreads();

    if (t == 0) {
        float m = smax[0];
#pragma unroll
        for (int w = 1; w < THREADS / 32; w++) m = fmaxf(m, smax[w]);
        g_partial[row * CHUNKS + chunk] = m;
        __threadfence();
        int old = atomicAdd(&g_ctr[row], 1);
        slast = (old == CHUNKS - 1);
    }
    __syncthreads();

    // Last block of this row: 16 threads reduce 16 partials (partial mask!),
    // apply empty-mask fixup, write out, reset counter for graph replay.
    if (slast && t < CHUNKS) {
        float v = g_partial[row * CHUNKS + t];
#pragma unroll
        for (int o = CHUNKS / 2; o; o >>= 1)
            v = fmaxf(v, __shfl_xor_sync(0xffffu, v, o));
        if (t == 0) {
            out[row] = g_nonempty[b] ? v : 0.0f;
            g_ctr[row] = 0;
        }
    }
}

extern "C" void kernel_launch(void* const* d_in, const int* in_sizes, int n_in,
                              void* d_out, int out_size) {
    const float4* x     = (const float4*)d_in[0];
    const int4*   mask4 = (const int4*)d_in[1];
    float*        out   = (float*)d_out;

    pack_kernel<<<NCID * PACKQ, THREADS>>>(mask4);
    pool_kernel<<<NROWS * CHUNKS, THREADS>>>(x, out);
}